// round 1
// baseline (speedup 1.0000x reference)
#include <cuda_runtime.h>
#include <cstdint>

// Problem constants
#define BB 8192
#define DD 1024
#define HH 1024
#define EE 16

// ---------------- scratch (device globals: allocation-free rule) -------------
__device__ float g_xt [(size_t)BB * DD];          //  32 MB  tf32-rounded x
__device__ float g_W1t[(size_t)EE * DD * HH];     //  64 MB  tf32-rounded W1
__device__ float g_W2t[(size_t)EE * HH * HH];     //  64 MB  tf32-rounded W2
__device__ float g_h1 [(size_t)EE * BB * HH];     // 512 MB  h1 (later reused as h3)
__device__ float g_h2 [(size_t)EE * BB * HH];     // 512 MB  h2
__device__ float g_f  [(size_t)BB * EE];          // 512 KB  expert scalars

// ---------------- helpers ----------------------------------------------------
__device__ __forceinline__ float tf32r(float x) {
    uint32_t o;
    asm("cvt.rna.tf32.f32 %0, %1;" : "=r"(o) : "f"(x));
    return __uint_as_float(o);
}

__device__ __forceinline__ void cp_async16(void* smem, const void* gmem) {
    uint32_t s = (uint32_t)__cvta_generic_to_shared(smem);
    asm volatile("cp.async.cg.shared.global [%0], [%1], 16;\n" :: "r"(s), "l"(gmem));
}
__device__ __forceinline__ void cp_commit() { asm volatile("cp.async.commit_group;\n"); }
template <int N>
__device__ __forceinline__ void cp_wait() { asm volatile("cp.async.wait_group %0;\n" :: "n"(N)); }

__device__ __forceinline__ void mma_tf32(float* d, const uint32_t* a, const uint32_t* b) {
    asm volatile(
        "mma.sync.aligned.m16n8k8.row.col.f32.tf32.tf32.f32 "
        "{%0,%1,%2,%3}, {%4,%5,%6,%7}, {%8,%9}, {%0,%1,%2,%3};"
        : "+f"(d[0]), "+f"(d[1]), "+f"(d[2]), "+f"(d[3])
        : "r"(a[0]), "r"(a[1]), "r"(a[2]), "r"(a[3]), "r"(b[0]), "r"(b[1]));
}

// ---------------- convert: rna-round x, W1, W2 to tf32 bits -------------------
__global__ void convert_tf32(const float* __restrict__ x,
                             const float* __restrict__ W1,
                             const float* __restrict__ W2) {
    size_t i = (size_t)blockIdx.x * blockDim.x + threadIdx.x;
    if (i < (size_t)BB * DD) g_xt[i] = tf32r(x[i]);
    if (i < (size_t)EE * DD * HH) {
        g_W1t[i] = tf32r(W1[i]);
        g_W2t[i] = tf32r(W2[i]);
    }
}

// ---------------- batched expert GEMM -----------------------------------------
// C[e][b][n] = act( A[e][b][:] . W[e][:][n] + bias[e][n] )
// M=8192, N=K=1024.  CTA tile 128x128, K-tile 16, double-buffered cp.async.
// STAGE 0: A=g_xt (shared across e), W=g_W1t, C=g_h1, act=sigmoid (tf32-rounded)
// STAGE 1: A=g_h1,                   W=g_W2t, C=g_h2, act=relu    (tf32-rounded)
// STAGE 2: A=g_h2,                   W=g_W2t, C=g_h1, act=none    (full fp32)
#define GM BB
#define GN HH
#define GK 1024
#define BM 128
#define BN 128
#define BK 16
#define KT (GK / BK)

template <int STAGE>
__global__ __launch_bounds__(256, 2) void expert_gemm(const float* __restrict__ bias_all) {
    __shared__ float As[2][BM][20];    // pad 16->20: conflict-free frag reads
    __shared__ float Bs[2][BK][136];   // pad 128->136: conflict-free frag reads

    const int e  = blockIdx.z;
    const int m0 = blockIdx.y * BM;
    const int n0 = blockIdx.x * BN;

    const float* A = (STAGE == 0) ? g_xt : (STAGE == 1 ? g_h1 : g_h2);
    if (STAGE != 0) A += (size_t)e * GM * GK;
    const float* Wp = ((STAGE == 0) ? g_W1t : g_W2t) + (size_t)e * GK * GN;
    float* C = ((STAGE == 0) ? g_h1 : (STAGE == 1 ? g_h2 : g_h1)) + (size_t)e * GM * GN;
    const float* biasE = bias_all + (size_t)e * GN;

    const int tid  = threadIdx.x;
    const int lane = tid & 31;
    const int warp = tid >> 5;
    const int wm   = warp & 1;   // 2 warps over M
    const int wn   = warp >> 1;  // 4 warps over N

    float acc[4][4][4];
#pragma unroll
    for (int mi = 0; mi < 4; mi++)
#pragma unroll
        for (int ni = 0; ni < 4; ni++)
#pragma unroll
            for (int r = 0; r < 4; r++) acc[mi][ni][r] = 0.0f;

    // tile loaders: 512 x 16B chunks each, 2 per thread
    auto loadA = [&](int buf, int kt) {
#pragma unroll
        for (int t = 0; t < 2; t++) {
            int j = tid + t * 256;
            int row = j >> 2, seg = j & 3;
            cp_async16(&As[buf][row][seg * 4],
                       A + (size_t)(m0 + row) * GK + kt * BK + seg * 4);
        }
    };
    auto loadB = [&](int buf, int kt) {
#pragma unroll
        for (int t = 0; t < 2; t++) {
            int j = tid + t * 256;
            int row = j >> 5, seg = j & 31;
            cp_async16(&Bs[buf][row][seg * 4],
                       Wp + (size_t)(kt * BK + row) * GN + n0 + seg * 4);
        }
    };

    loadA(0, 0);
    loadB(0, 0);
    cp_commit();

    const int ar = lane >> 2;   // fragment row-group
    const int ac = lane & 3;    // fragment col-in-group

    for (int kt = 0; kt < KT; ++kt) {
        const int buf = kt & 1;
        if (kt + 1 < KT) {
            loadA(buf ^ 1, kt + 1);
            loadB(buf ^ 1, kt + 1);
            cp_commit();
            cp_wait<1>();
        } else {
            cp_wait<0>();
        }
        __syncthreads();

#pragma unroll
        for (int ks = 0; ks < 2; ++ks) {
            const int k = ks * 8;
            uint32_t afr[4][4], bfr[4][2];
#pragma unroll
            for (int mi = 0; mi < 4; mi++) {
                int r = wm * 64 + mi * 16 + ar;
                afr[mi][0] = __float_as_uint(As[buf][r][k + ac]);
                afr[mi][1] = __float_as_uint(As[buf][r + 8][k + ac]);
                afr[mi][2] = __float_as_uint(As[buf][r][k + 4 + ac]);
                afr[mi][3] = __float_as_uint(As[buf][r + 8][k + 4 + ac]);
            }
#pragma unroll
            for (int ni = 0; ni < 4; ni++) {
                int c = wn * 32 + ni * 8 + ar;
                bfr[ni][0] = __float_as_uint(Bs[buf][k + ac][c]);
                bfr[ni][1] = __float_as_uint(Bs[buf][k + 4 + ac][c]);
            }
#pragma unroll
            for (int mi = 0; mi < 4; mi++)
#pragma unroll
                for (int ni = 0; ni < 4; ni++) mma_tf32(acc[mi][ni], afr[mi], bfr[ni]);
        }
        __syncthreads();
    }

    // epilogue
#pragma unroll
    for (int mi = 0; mi < 4; mi++) {
        int r0 = m0 + wm * 64 + mi * 16 + ar;
#pragma unroll
        for (int ni = 0; ni < 4; ni++) {
            int c0 = n0 + wn * 32 + ni * 8 + ac * 2;
            float bv0 = biasE[c0], bv1 = biasE[c0 + 1];
            float v0 = acc[mi][ni][0] + bv0;
            float v1 = acc[mi][ni][1] + bv1;
            float v2 = acc[mi][ni][2] + bv0;
            float v3 = acc[mi][ni][3] + bv1;
            if (STAGE == 0) {
                v0 = tf32r(1.0f / (1.0f + __expf(-v0)));
                v1 = tf32r(1.0f / (1.0f + __expf(-v1)));
                v2 = tf32r(1.0f / (1.0f + __expf(-v2)));
                v3 = tf32r(1.0f / (1.0f + __expf(-v3)));
            } else if (STAGE == 1) {
                v0 = tf32r(fmaxf(v0, 0.0f));
                v1 = tf32r(fmaxf(v1, 0.0f));
                v2 = tf32r(fmaxf(v2, 0.0f));
                v3 = tf32r(fmaxf(v3, 0.0f));
            }
            *(float2*)&C[(size_t)r0 * GN + c0]       = make_float2(v0, v1);
            *(float2*)&C[(size_t)(r0 + 8) * GN + c0] = make_float2(v2, v3);
        }
    }
}

// ---------------- f[b,e] = h3[e][b][:] . Wo[e][:] + bo[e] ---------------------
__global__ void f_kernel(const float* __restrict__ Wo, const float* __restrict__ bo) {
    const int lane = threadIdx.x & 31;
    const int w    = threadIdx.x >> 5;
    const int b    = blockIdx.x * 8 + w;
    const int e    = blockIdx.y;

    const float4* row = (const float4*)(g_h1 + ((size_t)e * BB + b) * HH);
    const float4* wo  = (const float4*)(Wo + (size_t)e * HH);
    float s = 0.0f;
#pragma unroll
    for (int i = 0; i < 8; i++) {
        float4 hv = row[i * 32 + lane];
        float4 wv = wo[i * 32 + lane];
        s += hv.x * wv.x + hv.y * wv.y + hv.z * wv.z + hv.w * wv.w;
    }
#pragma unroll
    for (int off = 16; off; off >>= 1) s += __shfl_xor_sync(0xFFFFFFFFu, s, off);
    if (lane == 0) g_f[(size_t)b * EE + e] = s + bo[e];
}

// ---------------- gates + final mix -------------------------------------------
// warp-per-row: z1/z2 = x.Wg + bg, softmax over E=16, out = sum_e g*f
__global__ void gate_kernel(const float* __restrict__ x,
                            const float* __restrict__ Wg1, const float* __restrict__ bg1,
                            const float* __restrict__ Wg2, const float* __restrict__ bg2,
                            float* __restrict__ out) {
    __shared__ float sm[8][32][33];
    const int lane = threadIdx.x & 31;
    const int w    = threadIdx.x >> 5;
    const int b    = blockIdx.x * 8 + w;

    const float* xr = x + (size_t)b * DD;
    float a1[16], a2[16];
#pragma unroll
    for (int v = 0; v < 16; v++) { a1[v] = 0.0f; a2[v] = 0.0f; }

    for (int i = 0; i < 32; i++) {
        int d = i * 32 + lane;
        float xv = xr[d];
        const float4* w1 = (const float4*)(Wg1 + (size_t)d * EE);
        const float4* w2 = (const float4*)(Wg2 + (size_t)d * EE);
#pragma unroll
        for (int j = 0; j < 4; j++) {
            float4 v1 = w1[j];
            a1[4 * j + 0] += xv * v1.x; a1[4 * j + 1] += xv * v1.y;
            a1[4 * j + 2] += xv * v1.z; a1[4 * j + 3] += xv * v1.w;
            float4 v2 = w2[j];
            a2[4 * j + 0] += xv * v2.x; a2[4 * j + 1] += xv * v2.y;
            a2[4 * j + 2] += xv * v2.z; a2[4 * j + 3] += xv * v2.w;
        }
    }

    // transpose via shared: lane -> value index (0..15 gate1, 16..31 gate2)
#pragma unroll
    for (int v = 0; v < 16; v++) {
        sm[w][v][lane]      = a1[v];
        sm[w][16 + v][lane] = a2[v];
    }
    __syncwarp();
    float z = 0.0f;
#pragma unroll
    for (int t = 0; t < 32; t++) z += sm[w][lane][t];
    z += (lane < 16) ? bg1[lane] : bg2[lane - 16];

    // softmax within each 16-lane group
    float mx = z;
#pragma unroll
    for (int off = 8; off; off >>= 1) mx = fmaxf(mx, __shfl_xor_sync(0xFFFFFFFFu, mx, off));
    float ez = __expf(z - mx);
    float s = ez;
#pragma unroll
    for (int off = 8; off; off >>= 1) s += __shfl_xor_sync(0xFFFFFFFFu, s, off);
    float g = ez / s;

    float fv = g_f[(size_t)b * EE + (lane & 15)];
    float p = g * fv;
#pragma unroll
    for (int off = 8; off; off >>= 1) p += __shfl_xor_sync(0xFFFFFFFFu, p, off);

    if (lane == 0)  out[b] = p;
    if (lane == 16) out[BB + b] = p;
}

// ---------------- launch ------------------------------------------------------
extern "C" void kernel_launch(void* const* d_in, const int* in_sizes, int n_in,
                              void* d_out, int out_size) {
    const float* x   = (const float*)d_in[0];
    // d_in[1] = W1 (converted), d_in[3] = W2 (converted)
    const float* b1  = (const float*)d_in[2];
    const float* b2  = (const float*)d_in[4];
    const float* Wo  = (const float*)d_in[5];
    const float* bo  = (const float*)d_in[6];
    const float* Wg1 = (const float*)d_in[7];
    const float* bg1 = (const float*)d_in[8];
    const float* Wg2 = (const float*)d_in[9];
    const float* bg2 = (const float*)d_in[10];
    float* out = (float*)d_out;

    const float* W1 = (const float*)d_in[1];
    const float* W2 = (const float*)d_in[3];

    convert_tf32<<<(EE * DD * HH) / 256, 256>>>(x, W1, W2);

    dim3 ggrid(GN / BN, GM / BM, EE);  // (8, 64, 16)
    expert_gemm<0><<<ggrid, 256>>>(b1);
    expert_gemm<1><<<ggrid, 256>>>(b2);
    expert_gemm<2><<<ggrid, 256>>>(b2);

    f_kernel<<<dim3(BB / 8, EE), 256>>>(Wo, bo);
    gate_kernel<<<BB / 8, 256>>>(x, Wg1, bg1, Wg2, bg2, out);
}

// round 4
// speedup vs baseline: 1.5264x; 1.5264x over previous
#include <cuda_runtime.h>
#include <cstdint>

// Problem constants
#define BB 8192
#define DD 1024
#define HH 1024
#define EE 16

#define GM BB
#define GN HH
#define GK 1024
#define BM 128
#define BN 128
#define BK 32
#define KT (GK / BK)     // 32 k-tiles
#define NSTG 3

// smem layout (per stage): A 128 rows x 36 floats (pad), B 32 rows x 136 floats (pad)
#define A_STRIDE 36
#define B_STRIDE 136
#define A_BYTES (BM * A_STRIDE * 4)          // 18432
#define B_BYTES (BK * B_STRIDE * 4)          // 17408
#define STG_BYTES (A_BYTES + B_BYTES)        // 35840
#define SMEM_TOTAL (NSTG * STG_BYTES)        // 107520

// ---------------- scratch (device globals: allocation-free rule) -------------
__device__ float g_xt [(size_t)BB * DD];          //  32 MB  tf32-rounded x
__device__ float g_W1t[(size_t)EE * DD * HH];     //  64 MB  tf32-rounded W1
__device__ float g_W2t[(size_t)EE * HH * HH];     //  64 MB  tf32-rounded W2
__device__ float g_h1 [(size_t)EE * BB * HH];     // 512 MB  h1 (GEMM1 out / GEMM2 in)
__device__ float g_f  [(size_t)BB * EE];          // 512 KB  expert scalars (atomic acc)
__device__ float g_v  [(size_t)EE * HH];          //  64 KB  folded W2.Wo
__device__ float g_c  [EE];                       //  folded b2.Wo + bo

// ---------------- helpers ----------------------------------------------------
__device__ __forceinline__ float tf32r(float x) {
    uint32_t o;
    asm("cvt.rna.tf32.f32 %0, %1;" : "=r"(o) : "f"(x));
    return __uint_as_float(o);
}
__device__ __forceinline__ void cp_async16(void* smem, const void* gmem) {
    uint32_t s = (uint32_t)__cvta_generic_to_shared(smem);
    asm volatile("cp.async.cg.shared.global [%0], [%1], 16;\n" :: "r"(s), "l"(gmem));
}
__device__ __forceinline__ void cp_commit() { asm volatile("cp.async.commit_group;\n"); }
template <int N>
__device__ __forceinline__ void cp_wait() { asm volatile("cp.async.wait_group %0;\n" :: "n"(N)); }

__device__ __forceinline__ void mma_tf32(float* d, const uint32_t* a, const uint32_t* b) {
    asm volatile(
        "mma.sync.aligned.m16n8k8.row.col.f32.tf32.tf32.f32 "
        "{%0,%1,%2,%3}, {%4,%5,%6,%7}, {%8,%9}, {%0,%1,%2,%3};"
        : "+f"(d[0]), "+f"(d[1]), "+f"(d[2]), "+f"(d[3])
        : "r"(a[0]), "r"(a[1]), "r"(a[2]), "r"(a[3]), "r"(b[0]), "r"(b[1]));
}

// ---------------- prep kernels ------------------------------------------------
__global__ void convert_tf32(const float* __restrict__ x,
                             const float* __restrict__ W1,
                             const float* __restrict__ W2) {
    size_t i = (size_t)blockIdx.x * blockDim.x + threadIdx.x;
    if (i < (size_t)BB * DD) g_xt[i] = tf32r(x[i]);
    g_W1t[i] = tf32r(W1[i]);
    g_W2t[i] = tf32r(W2[i]);
}

// v[e,h] = W2[e,h,:].Wo[e,:]  (full fp32; replaces GEMM3)
__global__ void fold_v(const float* __restrict__ W2, const float* __restrict__ Wo) {
    const int lane = threadIdx.x & 31;
    const int w    = threadIdx.x >> 5;
    const int e    = blockIdx.x;
    const int h    = blockIdx.y * 8 + w;
    const float4* row = (const float4*)(W2 + ((size_t)e * HH + h) * HH);
    const float4* wo  = (const float4*)(Wo + (size_t)e * HH);
    float s = 0.0f;
#pragma unroll
    for (int i = 0; i < 8; i++) {
        float4 a = row[i * 32 + lane];
        float4 b = wo[i * 32 + lane];
        s += a.x * b.x + a.y * b.y + a.z * b.z + a.w * b.w;
    }
#pragma unroll
    for (int off = 16; off; off >>= 1) s += __shfl_xor_sync(0xFFFFFFFFu, s, off);
    if (lane == 0) g_v[(size_t)e * HH + h] = s;
}

// c[e] = b2[e,:].Wo[e,:] + bo[e]
__global__ void fold_c(const float* __restrict__ b2, const float* __restrict__ Wo,
                       const float* __restrict__ bo) {
    const int lane = threadIdx.x & 31;
    const int e    = threadIdx.x >> 5;
    const float4* bb = (const float4*)(b2 + (size_t)e * HH);
    const float4* wo = (const float4*)(Wo + (size_t)e * HH);
    float s = 0.0f;
#pragma unroll
    for (int i = 0; i < 8; i++) {
        float4 a = bb[i * 32 + lane];
        float4 b = wo[i * 32 + lane];
        s += a.x * b.x + a.y * b.y + a.z * b.z + a.w * b.w;
    }
#pragma unroll
    for (int off = 16; off; off >>= 1) s += __shfl_xor_sync(0xFFFFFFFFu, s, off);
    if (lane == 0) g_c[e] = s + bo[e];
}

__global__ void zero_f() {
    g_f[(size_t)blockIdx.x * blockDim.x + threadIdx.x] = 0.0f;
}

// ---------------- batched expert GEMM (mma.sync tf32) -------------------------
// STAGE 0: h1[e,b,n] = tf32r(sigmoid(x[b,:].W1[e,:,n] + b1[e,n]))
// STAGE 1: f[b,e]   += sum_n relu(h1[e,b,:].W2[e,:,n] + b2[e,n]) * v[e,n]
// CTA 128 threads, 4 warps (2x2), warp tile 64x64, CTA tile 128x128, BK=32.
template <int STAGE>
__global__ __launch_bounds__(128) void expert_gemm(const float* __restrict__ bias_all) {
    extern __shared__ char smem[];

    const int e  = blockIdx.z;
    const int m0 = blockIdx.y * BM;
    const int n0 = blockIdx.x * BN;

    const float* A = (STAGE == 0) ? g_xt : (g_h1 + (size_t)e * BB * GK);
    const float* Wp = ((STAGE == 0) ? g_W1t : g_W2t) + ((size_t)e << 20);
    const float* bias = bias_all + (size_t)e * HH;

    const int tid  = threadIdx.x;
    const int lane = tid & 31;
    const int warp = tid >> 5;
    const int wm   = warp & 1;   // 2 warps over M
    const int wn   = warp >> 1;  // 2 warps over N
    const int ar   = lane >> 2;
    const int ac   = lane & 3;

    float acc[4][8][4];
#pragma unroll
    for (int mi = 0; mi < 4; mi++)
#pragma unroll
        for (int ni = 0; ni < 8; ni++)
#pragma unroll
            for (int r = 0; r < 4; r++) acc[mi][ni][r] = 0.0f;

    const float* Agm = A + (size_t)m0 * GK;
    const float* Bgm = Wp + n0;

    auto load_tile = [&](int s, int kt) {
        char* a0 = smem + s * STG_BYTES;
        char* b0 = a0 + A_BYTES;
        const float* Ag = Agm + kt * BK;
        const float* Bg = Bgm + (size_t)kt * BK * GN;
#pragma unroll
        for (int t = 0; t < 8; t++) {             // A: 1024 chunks / 128 thr
            int j = tid + t * 128;
            int row = j >> 3, seg = j & 7;
            cp_async16(a0 + row * (A_STRIDE * 4) + seg * 16,
                       Ag + (size_t)row * GK + seg * 4);
        }
#pragma unroll
        for (int t = 0; t < 8; t++) {             // B: 1024 chunks / 128 thr
            int j = tid + t * 128;
            int row = j >> 5, seg = j & 31;
            cp_async16(b0 + row * (B_STRIDE * 4) + seg * 16,
                       Bg + (size_t)row * GN + seg * 4);
        }
    };

#pragma unroll
    for (int s = 0; s < NSTG - 1; s++) {
        load_tile(s, s);
        cp_commit();
    }

    for (int kt = 0; kt < KT; ++kt) {
        const int s = kt % NSTG;
        cp_wait<NSTG - 2>();
        __syncthreads();
        if (kt + NSTG - 1 < KT) load_tile((kt + NSTG - 1) % NSTG, kt + NSTG - 1);
        cp_commit();

        const float(*As)[A_STRIDE] = (const float(*)[A_STRIDE])(smem + s * STG_BYTES);
        const float(*Bs)[B_STRIDE] = (const float(*)[B_STRIDE])(smem + s * STG_BYTES + A_BYTES);

#pragma unroll
        for (int ks = 0; ks < 4; ++ks) {
            const int k = ks * 8;
            uint32_t afr[4][4], bfr[8][2];
#pragma unroll
            for (int mi = 0; mi < 4; mi++) {
                int r = wm * 64 + mi * 16 + ar;
                afr[mi][0] = __float_as_uint(As[r][k + ac]);
                afr[mi][1] = __float_as_uint(As[r + 8][k + ac]);
                afr[mi][2] = __float_as_uint(As[r][k + 4 + ac]);
                afr[mi][3] = __float_as_uint(As[r + 8][k + 4 + ac]);
            }
#pragma unroll
            for (int ni = 0; ni < 8; ni++) {
                int c = wn * 64 + ni * 8 + ar;
                bfr[ni][0] = __float_as_uint(Bs[k + ac][c]);
                bfr[ni][1] = __float_as_uint(Bs[k + 4 + ac][c]);
            }
#pragma unroll
            for (int mi = 0; mi < 4; mi++)
#pragma unroll
                for (int ni = 0; ni < 8; ni++) mma_tf32(acc[mi][ni], afr[mi], bfr[ni]);
        }
        __syncthreads();
    }

    if (STAGE == 0) {
        float* C = g_h1 + (size_t)e * BB * HH;
#pragma unroll
        for (int mi = 0; mi < 4; mi++) {
            int r0 = m0 + wm * 64 + mi * 16 + ar;
#pragma unroll
            for (int ni = 0; ni < 8; ni++) {
                int c0 = n0 + wn * 64 + ni * 8 + ac * 2;
                float bv0 = bias[c0], bv1 = bias[c0 + 1];
                float v0 = tf32r(1.0f / (1.0f + __expf(-(acc[mi][ni][0] + bv0))));
                float v1 = tf32r(1.0f / (1.0f + __expf(-(acc[mi][ni][1] + bv1))));
                float v2 = tf32r(1.0f / (1.0f + __expf(-(acc[mi][ni][2] + bv0))));
                float v3 = tf32r(1.0f / (1.0f + __expf(-(acc[mi][ni][3] + bv1))));
                *(float2*)&C[(size_t)r0 * HH + c0]       = make_float2(v0, v1);
                *(float2*)&C[(size_t)(r0 + 8) * HH + c0] = make_float2(v2, v3);
            }
        }
    } else {
        // f epilogue: relu(acc + b2[c]) * v[e,c], row-reduce, atomicAdd
        const float* ve = g_v + (size_t)e * HH;
#pragma unroll
        for (int mi = 0; mi < 4; mi++) {
            int r0 = m0 + wm * 64 + mi * 16 + ar;
            float s0 = 0.0f, s1 = 0.0f;
#pragma unroll
            for (int ni = 0; ni < 8; ni++) {
                int c0 = n0 + wn * 64 + ni * 8 + ac * 2;
                float bv0 = bias[c0], bv1 = bias[c0 + 1];
                float vv0 = ve[c0],   vv1 = ve[c0 + 1];
                s0 += fmaxf(acc[mi][ni][0] + bv0, 0.0f) * vv0
                    + fmaxf(acc[mi][ni][1] + bv1, 0.0f) * vv1;
                s1 += fmaxf(acc[mi][ni][2] + bv0, 0.0f) * vv0
                    + fmaxf(acc[mi][ni][3] + bv1, 0.0f) * vv1;
            }
            // reduce over the 4 lanes (ac) sharing this row
            s0 += __shfl_xor_sync(0xFFFFFFFFu, s0, 1);
            s0 += __shfl_xor_sync(0xFFFFFFFFu, s0, 2);
            s1 += __shfl_xor_sync(0xFFFFFFFFu, s1, 1);
            s1 += __shfl_xor_sync(0xFFFFFFFFu, s1, 2);
            if (ac == 0) {
                atomicAdd(&g_f[(size_t)r0 * EE + e], s0);
                atomicAdd(&g_f[(size_t)(r0 + 8) * EE + e], s1);
            }
        }
    }
}

// ---------------- gates + final mix -------------------------------------------
__global__ void gate_kernel(const float* __restrict__ x,
                            const float* __restrict__ Wg1, const float* __restrict__ bg1,
                            const float* __restrict__ Wg2, const float* __restrict__ bg2,
                            float* __restrict__ out) {
    __shared__ float sm[8][32][33];
    const int lane = threadIdx.x & 31;
    const int w    = threadIdx.x >> 5;
    const int b    = blockIdx.x * 8 + w;

    const float* xr = x + (size_t)b * DD;
    float a1[16], a2[16];
#pragma unroll
    for (int v = 0; v < 16; v++) { a1[v] = 0.0f; a2[v] = 0.0f; }

    for (int i = 0; i < 32; i++) {
        int d = i * 32 + lane;
        float xv = xr[d];
        const float4* w1 = (const float4*)(Wg1 + (size_t)d * EE);
        const float4* w2 = (const float4*)(Wg2 + (size_t)d * EE);
#pragma unroll
        for (int j = 0; j < 4; j++) {
            float4 v1 = w1[j];
            a1[4 * j + 0] += xv * v1.x; a1[4 * j + 1] += xv * v1.y;
            a1[4 * j + 2] += xv * v1.z; a1[4 * j + 3] += xv * v1.w;
            float4 v2 = w2[j];
            a2[4 * j + 0] += xv * v2.x; a2[4 * j + 1] += xv * v2.y;
            a2[4 * j + 2] += xv * v2.z; a2[4 * j + 3] += xv * v2.w;
        }
    }
#pragma unroll
    for (int v = 0; v < 16; v++) {
        sm[w][v][lane]      = a1[v];
        sm[w][16 + v][lane] = a2[v];
    }
    __syncwarp();
    float z = 0.0f;
#pragma unroll
    for (int t = 0; t < 32; t++) z += sm[w][lane][t];
    z += (lane < 16) ? bg1[lane] : bg2[lane - 16];

    float mx = z;
#pragma unroll
    for (int off = 8; off; off >>= 1) mx = fmaxf(mx, __shfl_xor_sync(0xFFFFFFFFu, mx, off));
    float ez = __expf(z - mx);
    float s = ez;
#pragma unroll
    for (int off = 8; off; off >>= 1) s += __shfl_xor_sync(0xFFFFFFFFu, s, off);
    float g = ez / s;

    float fv = g_f[(size_t)b * EE + (lane & 15)] + g_c[lane & 15];
    float p = g * fv;
#pragma unroll
    for (int off = 8; off; off >>= 1) p += __shfl_xor_sync(0xFFFFFFFFu, p, off);

    if (lane == 0)  out[b] = p;
    if (lane == 16) out[BB + b] = p;
}

// ---------------- launch ------------------------------------------------------
extern "C" void kernel_launch(void* const* d_in, const int* in_sizes, int n_in,
                              void* d_out, int out_size) {
    const float* x   = (const float*)d_in[0];
    const float* W1  = (const float*)d_in[1];
    const float* b1  = (const float*)d_in[2];
    const float* W2  = (const float*)d_in[3];
    const float* b2  = (const float*)d_in[4];
    const float* Wo  = (const float*)d_in[5];
    const float* bo  = (const float*)d_in[6];
    const float* Wg1 = (const float*)d_in[7];
    const float* bg1 = (const float*)d_in[8];
    const float* Wg2 = (const float*)d_in[9];
    const float* bg2 = (const float*)d_in[10];
    float* out = (float*)d_out;

    cudaFuncSetAttribute(expert_gemm<0>, cudaFuncAttributeMaxDynamicSharedMemorySize, SMEM_TOTAL);
    cudaFuncSetAttribute(expert_gemm<1>, cudaFuncAttributeMaxDynamicSharedMemorySize, SMEM_TOTAL);

    convert_tf32<<<(EE * DD * HH) / 256, 256>>>(x, W1, W2);
    fold_v<<<dim3(EE, HH / 8), 256>>>(W2, Wo);
    fold_c<<<1, 512>>>(b2, Wo, bo);
    zero_f<<<(BB * EE) / 256, 256>>>();

    dim3 ggrid(GN / BN, GM / BM, EE);   // (8, 64, 16)
    expert_gemm<0><<<ggrid, 128, SMEM_TOTAL>>>(b1);
    expert_gemm<1><<<ggrid, 128, SMEM_TOTAL>>>(b2);

    gate_kernel<<<BB / 8, 256>>>(x, Wg1, bg1, Wg2, bg2, out);
}

// round 5
// speedup vs baseline: 3.2823x; 2.1503x over previous
#include <cuda_runtime.h>
#include <cuda_fp16.h>
#include <cstdint>

// Problem constants
#define BB 8192
#define DD 1024
#define HH 1024
#define EE 16

#define GM BB
#define GN HH
#define GK 1024
#define BM 128
#define BN 128
#define BKH 64           // k halves per tile (= 128 bytes per row)
#define KTH (GK / BKH)   // 16 k-tiles
#define NSTG 3

#define TILE_BYTES (128 * 128)          // 16 KB (128 rows x 128B)
#define STG_BYTES (2 * TILE_BYTES)      // A + B = 32 KB
#define SMEM_TOTAL (NSTG * STG_BYTES)   // 96 KB

// ---------------- scratch (device globals: allocation-free rule) -------------
__device__ __half g_xh [(size_t)BB * DD];         //  16 MB  fp16 x
__device__ __half g_W1h[(size_t)EE * DD * HH];    //  32 MB  W1^T fp16 [E][n][k]
__device__ __half g_W2h[(size_t)EE * HH * HH];    //  32 MB  W2^T fp16 [E][n][k]
__device__ __half g_h1 [(size_t)EE * BB * HH];    // 256 MB  h1 fp16
__device__ float  g_f  [(size_t)BB * EE];         // expert scalars (atomic acc)
__device__ float  g_v  [(size_t)EE * HH];         // folded W2.Wo (fp32 exact)
__device__ float  g_c  [EE];                      // folded b2.Wo + bo

// ---------------- helpers ----------------------------------------------------
__device__ __forceinline__ void cp_async16(uint32_t smem, const void* gmem) {
    asm volatile("cp.async.cg.shared.global [%0], [%1], 16;\n" :: "r"(smem), "l"(gmem));
}
__device__ __forceinline__ void cp_commit() { asm volatile("cp.async.commit_group;\n"); }
template <int N>
__device__ __forceinline__ void cp_wait() { asm volatile("cp.async.wait_group %0;\n" :: "n"(N)); }

__device__ __forceinline__ void ldsm4(uint32_t& r0, uint32_t& r1, uint32_t& r2, uint32_t& r3,
                                      uint32_t addr) {
    asm volatile("ldmatrix.sync.aligned.m8n8.x4.shared.b16 {%0,%1,%2,%3}, [%4];"
                 : "=r"(r0), "=r"(r1), "=r"(r2), "=r"(r3) : "r"(addr));
}
__device__ __forceinline__ void mma_f16(float* d, const uint32_t* a, const uint32_t* b) {
    asm volatile(
        "mma.sync.aligned.m16n8k16.row.col.f32.f16.f16.f32 "
        "{%0,%1,%2,%3}, {%4,%5,%6,%7}, {%8,%9}, {%0,%1,%2,%3};"
        : "+f"(d[0]), "+f"(d[1]), "+f"(d[2]), "+f"(d[3])
        : "r"(a[0]), "r"(a[1]), "r"(a[2]), "r"(a[3]), "r"(b[0]), "r"(b[1]));
}

// ---------------- prep kernels ------------------------------------------------
__global__ void convert_x(const float* __restrict__ x) {
    size_t i = (size_t)blockIdx.x * blockDim.x + threadIdx.x;
    g_xh[i] = __float2half_rn(x[i]);
}

// transpose W1, W2 to [E][n][k] fp16
__global__ void transpose_w(const float* __restrict__ W1, const float* __restrict__ W2) {
    __shared__ float t1[32][33], t2[32][33];
    const int e = blockIdx.z;
    const int c0 = blockIdx.x * 32;   // source col (n)
    const int r0 = blockIdx.y * 32;   // source row (k)
    const size_t eo = (size_t)e << 20;
    const int tx = threadIdx.x, ty = threadIdx.y;
#pragma unroll
    for (int i = 0; i < 32; i += 8) {
        t1[ty + i][tx] = W1[eo + (size_t)(r0 + ty + i) * 1024 + c0 + tx];
        t2[ty + i][tx] = W2[eo + (size_t)(r0 + ty + i) * 1024 + c0 + tx];
    }
    __syncthreads();
#pragma unroll
    for (int i = 0; i < 32; i += 8) {
        g_W1h[eo + (size_t)(c0 + ty + i) * 1024 + r0 + tx] = __float2half_rn(t1[tx][ty + i]);
        g_W2h[eo + (size_t)(c0 + ty + i) * 1024 + r0 + tx] = __float2half_rn(t2[tx][ty + i]);
    }
}

// v[e,h] = W2[e,h,:].Wo[e,:]  (full fp32; replaces GEMM3)
__global__ void fold_v(const float* __restrict__ W2, const float* __restrict__ Wo) {
    const int lane = threadIdx.x & 31;
    const int w    = threadIdx.x >> 5;
    const int e    = blockIdx.x;
    const int h    = blockIdx.y * 8 + w;
    const float4* row = (const float4*)(W2 + ((size_t)e * HH + h) * HH);
    const float4* wo  = (const float4*)(Wo + (size_t)e * HH);
    float s = 0.0f;
#pragma unroll
    for (int i = 0; i < 8; i++) {
        float4 a = row[i * 32 + lane];
        float4 b = wo[i * 32 + lane];
        s += a.x * b.x + a.y * b.y + a.z * b.z + a.w * b.w;
    }
#pragma unroll
    for (int off = 16; off; off >>= 1) s += __shfl_xor_sync(0xFFFFFFFFu, s, off);
    if (lane == 0) g_v[(size_t)e * HH + h] = s;
}

__global__ void fold_c(const float* __restrict__ b2, const float* __restrict__ Wo,
                       const float* __restrict__ bo) {
    const int lane = threadIdx.x & 31;
    const int e    = threadIdx.x >> 5;
    const float4* bb = (const float4*)(b2 + (size_t)e * HH);
    const float4* wo = (const float4*)(Wo + (size_t)e * HH);
    float s = 0.0f;
#pragma unroll
    for (int i = 0; i < 8; i++) {
        float4 a = bb[i * 32 + lane];
        float4 b = wo[i * 32 + lane];
        s += a.x * b.x + a.y * b.y + a.z * b.z + a.w * b.w;
    }
#pragma unroll
    for (int off = 16; off; off >>= 1) s += __shfl_xor_sync(0xFFFFFFFFu, s, off);
    if (lane == 0) g_c[e] = s + bo[e];
}

__global__ void zero_f() {
    g_f[(size_t)blockIdx.x * blockDim.x + threadIdx.x] = 0.0f;
}

// ---------------- batched expert GEMM (mma.sync fp16, ldmatrix) ---------------
// STAGE 0: h1[e,b,n] = fp16(sigmoid(x[b,:].W1[e,:,n] + b1[e,n]))
// STAGE 1: f[b,e]   += sum_n relu(h1[e,b,:].W2[e,:,n] + b2[e,n]) * v[e,n]
// CTA 128 threads (2x2 warps), warp tile 64x64, CTA tile 128x128, BK=64 halves.
template <int STAGE>
__global__ __launch_bounds__(128) void expert_gemm(const float* __restrict__ bias_all) {
    extern __shared__ char smem[];
    const uint32_t sbase = (uint32_t)__cvta_generic_to_shared(smem);

    const int e  = blockIdx.z;
    const int m0 = blockIdx.y * BM;
    const int n0 = blockIdx.x * BN;

    const __half* A  = (STAGE == 0) ? g_xh : (g_h1 + (size_t)e * BB * GK);
    const __half* Bt = ((STAGE == 0) ? g_W1h : g_W2h) + ((size_t)e << 20);
    const float* bias = bias_all + (size_t)e * HH;

    const int tid  = threadIdx.x;
    const int lane = tid & 31;
    const int warp = tid >> 5;
    const int wm   = warp & 1;   // 2 warps over M
    const int wn   = warp >> 1;  // 2 warps over N
    const int ar   = lane >> 2;
    const int ac   = lane & 3;
    const int g    = lane >> 3;  // ldmatrix lane group 0..3
    const int rl   = lane & 7;

    float acc[4][8][4];
#pragma unroll
    for (int mi = 0; mi < 4; mi++)
#pragma unroll
        for (int ni = 0; ni < 8; ni++)
#pragma unroll
            for (int r = 0; r < 4; r++) acc[mi][ni][r] = 0.0f;

    const __half* Agm = A + (size_t)m0 * GK;
    const __half* Bgm = Bt + (size_t)n0 * GK;

    // load k-tile kt into stage s: A 128x128B, B 128x128B, xor-swizzled 16B chunks
    auto load_tile = [&](int s, int kt) {
        const uint32_t a0 = sbase + s * STG_BYTES;
        const uint32_t b0 = a0 + TILE_BYTES;
        const __half* Ag = Agm + kt * BKH;
        const __half* Bg = Bgm + kt * BKH;
#pragma unroll
        for (int t = 0; t < 8; t++) {
            int j = tid + t * 128;
            int row = j >> 3, c = j & 7;
            cp_async16(a0 + row * 128 + (((c ^ (row & 7)) << 4)),
                       Ag + (size_t)row * GK + c * 8);
        }
#pragma unroll
        for (int t = 0; t < 8; t++) {
            int j = tid + t * 128;
            int row = j >> 3, c = j & 7;
            cp_async16(b0 + row * 128 + (((c ^ (row & 7)) << 4)),
                       Bg + (size_t)row * GK + c * 8);
        }
    };

#pragma unroll
    for (int s = 0; s < NSTG - 1; s++) {
        load_tile(s, s);
        cp_commit();
    }

    for (int kt = 0; kt < KTH; ++kt) {
        const int s = kt % NSTG;
        cp_wait<NSTG - 2>();
        __syncthreads();
        if (kt + NSTG - 1 < KTH) load_tile((kt + NSTG - 1) % NSTG, kt + NSTG - 1);
        cp_commit();

        const uint32_t aB = sbase + s * STG_BYTES;
        const uint32_t bB = aB + TILE_BYTES;

#pragma unroll
        for (int ks = 0; ks < 4; ++ks) {
            uint32_t afr[4][4], bfr[8][2];
#pragma unroll
            for (int mi = 0; mi < 4; mi++) {
                // mat0: m0-7/k0-7, mat1: m8-15/k0-7, mat2: m0-7/k8-15, mat3: m8-15/k8-15
                int row = wm * 64 + mi * 16 + ((g & 1) << 3) + rl;
                int ck  = ks * 2 + (g >> 1);
                ldsm4(afr[mi][0], afr[mi][1], afr[mi][2], afr[mi][3],
                      aB + row * 128 + ((ck ^ (row & 7)) << 4));
            }
#pragma unroll
            for (int nj = 0; nj < 4; nj++) {
                // mat0: n0-7/k0-7 (b0 of ni), mat1: n0-7/k8-15 (b1), mat2/3: ni+1
                int row = wn * 64 + nj * 16 + ((g >> 1) << 3) + rl;
                int ck  = ks * 2 + (g & 1);
                ldsm4(bfr[2 * nj][0], bfr[2 * nj][1], bfr[2 * nj + 1][0], bfr[2 * nj + 1][1],
                      bB + row * 128 + ((ck ^ (row & 7)) << 4));
            }
#pragma unroll
            for (int mi = 0; mi < 4; mi++)
#pragma unroll
                for (int ni = 0; ni < 8; ni++) mma_f16(acc[mi][ni], afr[mi], bfr[ni]);
        }
        __syncthreads();
    }

    if (STAGE == 0) {
        __half* C = g_h1 + (size_t)e * BB * HH;
#pragma unroll
        for (int mi = 0; mi < 4; mi++) {
            int r0 = m0 + wm * 64 + mi * 16 + ar;
#pragma unroll
            for (int ni = 0; ni < 8; ni++) {
                int c0 = n0 + wn * 64 + ni * 8 + ac * 2;
                float bv0 = bias[c0], bv1 = bias[c0 + 1];
                float v0 = 1.0f / (1.0f + __expf(-(acc[mi][ni][0] + bv0)));
                float v1 = 1.0f / (1.0f + __expf(-(acc[mi][ni][1] + bv1)));
                float v2 = 1.0f / (1.0f + __expf(-(acc[mi][ni][2] + bv0)));
                float v3 = 1.0f / (1.0f + __expf(-(acc[mi][ni][3] + bv1)));
                *(__half2*)&C[(size_t)r0 * HH + c0]       = __floats2half2_rn(v0, v1);
                *(__half2*)&C[(size_t)(r0 + 8) * HH + c0] = __floats2half2_rn(v2, v3);
            }
        }
    } else {
        // f epilogue: relu(acc + b2[c]) * v[e,c], row-reduce, atomicAdd
        const float* ve = g_v + (size_t)e * HH;
#pragma unroll
        for (int mi = 0; mi < 4; mi++) {
            int r0 = m0 + wm * 64 + mi * 16 + ar;
            float s0 = 0.0f, s1 = 0.0f;
#pragma unroll
            for (int ni = 0; ni < 8; ni++) {
                int c0 = n0 + wn * 64 + ni * 8 + ac * 2;
                float bv0 = bias[c0], bv1 = bias[c0 + 1];
                float vv0 = ve[c0],   vv1 = ve[c0 + 1];
                s0 += fmaxf(acc[mi][ni][0] + bv0, 0.0f) * vv0
                    + fmaxf(acc[mi][ni][1] + bv1, 0.0f) * vv1;
                s1 += fmaxf(acc[mi][ni][2] + bv0, 0.0f) * vv0
                    + fmaxf(acc[mi][ni][3] + bv1, 0.0f) * vv1;
            }
            s0 += __shfl_xor_sync(0xFFFFFFFFu, s0, 1);
            s0 += __shfl_xor_sync(0xFFFFFFFFu, s0, 2);
            s1 += __shfl_xor_sync(0xFFFFFFFFu, s1, 1);
            s1 += __shfl_xor_sync(0xFFFFFFFFu, s1, 2);
            if (ac == 0) {
                atomicAdd(&g_f[(size_t)r0 * EE + e], s0);
                atomicAdd(&g_f[(size_t)(r0 + 8) * EE + e], s1);
            }
        }
    }
}

// ---------------- gates + final mix -------------------------------------------
__global__ void gate_kernel(const float* __restrict__ x,
                            const float* __restrict__ Wg1, const float* __restrict__ bg1,
                            const float* __restrict__ Wg2, const float* __restrict__ bg2,
                            float* __restrict__ out) {
    __shared__ float sm[8][32][33];
    const int lane = threadIdx.x & 31;
    const int w    = threadIdx.x >> 5;
    const int b    = blockIdx.x * 8 + w;

    const float* xr = x + (size_t)b * DD;
    float a1[16], a2[16];
#pragma unroll
    for (int v = 0; v < 16; v++) { a1[v] = 0.0f; a2[v] = 0.0f; }

    for (int i = 0; i < 32; i++) {
        int d = i * 32 + lane;
        float xv = xr[d];
        const float4* w1 = (const float4*)(Wg1 + (size_t)d * EE);
        const float4* w2 = (const float4*)(Wg2 + (size_t)d * EE);
#pragma unroll
        for (int j = 0; j < 4; j++) {
            float4 v1 = w1[j];
            a1[4 * j + 0] += xv * v1.x; a1[4 * j + 1] += xv * v1.y;
            a1[4 * j + 2] += xv * v1.z; a1[4 * j + 3] += xv * v1.w;
            float4 v2 = w2[j];
            a2[4 * j + 0] += xv * v2.x; a2[4 * j + 1] += xv * v2.y;
            a2[4 * j + 2] += xv * v2.z; a2[4 * j + 3] += xv * v2.w;
        }
    }
#pragma unroll
    for (int v = 0; v < 16; v++) {
        sm[w][v][lane]      = a1[v];
        sm[w][16 + v][lane] = a2[v];
    }
    __syncwarp();
    float z = 0.0f;
#pragma unroll
    for (int t = 0; t < 32; t++) z += sm[w][lane][t];
    z += (lane < 16) ? bg1[lane] : bg2[lane - 16];

    float mx = z;
#pragma unroll
    for (int off = 8; off; off >>= 1) mx = fmaxf(mx, __shfl_xor_sync(0xFFFFFFFFu, mx, off));
    float ez = __expf(z - mx);
    float s = ez;
#pragma unroll
    for (int off = 8; off; off >>= 1) s += __shfl_xor_sync(0xFFFFFFFFu, s, off);
    float g = ez / s;

    float fv = g_f[(size_t)b * EE + (lane & 15)] + g_c[lane & 15];
    float p = g * fv;
#pragma unroll
    for (int off = 8; off; off >>= 1) p += __shfl_xor_sync(0xFFFFFFFFu, p, off);

    if (lane == 0)  out[b] = p;
    if (lane == 16) out[BB + b] = p;
}

// ---------------- launch ------------------------------------------------------
extern "C" void kernel_launch(void* const* d_in, const int* in_sizes, int n_in,
                              void* d_out, int out_size) {
    const float* x   = (const float*)d_in[0];
    const float* W1  = (const float*)d_in[1];
    const float* b1  = (const float*)d_in[2];
    const float* W2  = (const float*)d_in[3];
    const float* b2  = (const float*)d_in[4];
    const float* Wo  = (const float*)d_in[5];
    const float* bo  = (const float*)d_in[6];
    const float* Wg1 = (const float*)d_in[7];
    const float* bg1 = (const float*)d_in[8];
    const float* Wg2 = (const float*)d_in[9];
    const float* bg2 = (const float*)d_in[10];
    float* out = (float*)d_out;

    cudaFuncSetAttribute(expert_gemm<0>, cudaFuncAttributeMaxDynamicSharedMemorySize, SMEM_TOTAL);
    cudaFuncSetAttribute(expert_gemm<1>, cudaFuncAttributeMaxDynamicSharedMemorySize, SMEM_TOTAL);

    convert_x<<<(BB * DD) / 256, 256>>>(x);
    transpose_w<<<dim3(32, 32, EE), dim3(32, 8)>>>(W1, W2);
    fold_v<<<dim3(EE, HH / 8), 256>>>(W2, Wo);
    fold_c<<<1, 512>>>(b2, Wo, bo);
    zero_f<<<(BB * EE) / 256, 256>>>();

    dim3 ggrid(GN / BN, GM / BM, EE);   // (8, 64, 16)
    expert_gemm<0><<<ggrid, 128, SMEM_TOTAL>>>(b1);
    expert_gemm<1><<<ggrid, 128, SMEM_TOTAL>>>(b2);

    gate_kernel<<<BB / 8, 256>>>(x, Wg1, bg1, Wg2, bg2, out);
}